// round 6
// baseline (speedup 1.0000x reference)
#include <cuda_runtime.h>
#include <math.h>

#define H    512
#define NH   8
#define DH   64
#define NLAY 2
#define NPRED 26
#define MAXF 5
#define FFD  2048
#define BSZ  16
#define TC   10
#define NOBJ 20
#define NP   380   /* NOBJ*(NOBJ-1) */
#define SP   516   /* padded smem row (floats) */

// ---------------- scratch (device globals; no allocation) ----------------
__device__ __align__(16) float g_px  [BSZ*MAXF*H];
__device__ __align__(16) float g_qkv [BSZ*MAXF*3*H];
__device__ __align__(16) float g_kv  [BSZ*TC*2*H];
__device__ __align__(16) float g_att [BSZ*MAXF*H];
__device__ __align__(16) float g_proj[BSZ*MAXF*H];
__device__ __align__(16) float g_ffh [BSZ*MAXF*FFD];
__device__ __align__(16) float g_ctx [BSZ*MAXF*H];
__device__ __align__(16) float g_sw  [BSZ*NOBJ*H];
__device__ __align__(16) float g_ow  [BSZ*NOBJ*H];
__device__ __align__(16) float g_cw  [BSZ*MAXF*H];
__device__ __align__(16) float g_wf  [27*H];
__device__ float g_bf [32];
__device__ int   g_cnt[32];   // zero-init; tails reset after use (graph-replay safe)

__device__ __forceinline__ float gelu_f(float x) {
    return 0.5f * x * (1.0f + erff(x * 0.70710678118654752440f));
}

// ---------------- warp-dot GEMM tile body (128 threads): 8m x 32n ----------------
// C[M,N] = act(A @ W^T + bias); W rows have leading dim ldw. K % 128 == 0.
// bcmod>0: A row m reads A + (m % bcmod)*K (broadcast rows).
__device__ __forceinline__ void gemm_body(
    const float* __restrict__ A, const float* __restrict__ W,
    const float* __restrict__ bias, float* __restrict__ C,
    int N, int K, int ldw, int act, int m0, int n0, int bcmod)
{
    int warp = threadIdx.x >> 5, lane = threadIdx.x & 31;
    n0 += warp * 8;
    const float* Ar[8];
    #pragma unroll
    for (int i = 0; i < 8; i++) {
        int m = m0 + i;
        int mm = bcmod ? (m % bcmod) : m;
        Ar[i] = A + (long)mm * K + lane * 4;
    }
    const float* Wb = W + (long)n0 * ldw + lane * 4;

    float acc[8][8];
    #pragma unroll
    for (int i = 0; i < 8; i++)
        #pragma unroll
        for (int j = 0; j < 8; j++) acc[i][j] = 0.f;

    for (int k = 0; k < K; k += 128) {
        float4 a[8];
        #pragma unroll
        for (int i = 0; i < 8; i++) a[i] = *(const float4*)(Ar[i] + k);
        #pragma unroll
        for (int j = 0; j < 8; j++) {
            float4 b = *(const float4*)(Wb + (long)j * ldw + k);
            #pragma unroll
            for (int i = 0; i < 8; i++)
                acc[i][j] += a[i].x * b.x + a[i].y * b.y + a[i].z * b.z + a[i].w * b.w;
        }
    }
    #pragma unroll
    for (int i = 0; i < 8; i++)
        #pragma unroll
        for (int j = 0; j < 8; j++) {
            float v = acc[i][j];
            v += __shfl_xor_sync(0xffffffffu, v, 16);
            v += __shfl_xor_sync(0xffffffffu, v, 8);
            v += __shfl_xor_sync(0xffffffffu, v, 4);
            v += __shfl_xor_sync(0xffffffffu, v, 2);
            v += __shfl_xor_sync(0xffffffffu, v, 1);
            acc[i][j] = v;
        }
    if (lane == 0) {
        #pragma unroll
        for (int j = 0; j < 8; j++) {
            int n = n0 + j;
            float bv = bias ? bias[n] : 0.f;
            #pragma unroll
            for (int i = 0; i < 8; i++) {
                float v = acc[i][j] + bv;
                if (act) v = gelu_f(v);
                C[(long)(m0 + i) * N + n] = v;
            }
        }
    }
}

__global__ void __launch_bounds__(128) k_gemm(
    const float* __restrict__ A, const float* __restrict__ W,
    const float* __restrict__ bias, float* __restrict__ C,
    int N, int K, int ldw, int act, int bcmod)
{
    gemm_body(A, W, bias, C, N, K, ldw, act, blockIdx.y * 8, blockIdx.x * 32, bcmod);
}

// combined CA q-proj (z=0) and kv-proj (z=1)
__global__ void __launch_bounds__(128) k_caqkv(
    const float* __restrict__ x, const float* __restrict__ tctx,
    const float* __restrict__ wq, const float* __restrict__ bq,
    const float* __restrict__ wkv, const float* __restrict__ bkv,
    float* __restrict__ qout, float* __restrict__ kvout, int Mq)
{
    if (blockIdx.z == 0) {
        if (blockIdx.x >= 16 || (int)blockIdx.y >= Mq / 8) return;
        gemm_body(x, wq, bq, qout, H, H, H, 0, blockIdx.y * 8, blockIdx.x * 32, 0);
    } else {
        gemm_body(tctx, wkv, bkv, kvout, 2 * H, H, H, 0, blockIdx.y * 8, blockIdx.x * 32, 0);
    }
}

// ---------------- fused attention sublayer ----------------
// grid (4, B); block 256. Each block: full attention for batch b (redundant x4),
// out-proj for its 128-col slice; last block per b does residual+LN.
__global__ void __launch_bounds__(256) k_attn(
    const float* __restrict__ qbuf, int qstride,
    const float* __restrict__ kvbuf, int kvstride, int koff, int voff,
    int Tq, int Tk,
    const float* __restrict__ ow, const float* __restrict__ ob,
    const float* __restrict__ res, int res_bcast,
    const float* __restrict__ lw, const float* __restrict__ lb,
    float* __restrict__ proj, float* __restrict__ xout)
{
    __shared__ float qs[MAXF * SP];
    __shared__ float ks[TC * SP];
    __shared__ float att[MAXF * SP];
    __shared__ float sc[NH * MAXF * (TC + 1)];
    __shared__ float r1[8], r2[8];
    __shared__ int s_last;

    int b = blockIdx.y;
    int t = threadIdx.x;

    for (int e = t; e < Tq * H; e += 256) {
        int r = e >> 9, c = e & (H - 1);
        qs[r * SP + c] = qbuf[(long)(b * Tq + r) * qstride + c];
    }
    for (int e = t; e < Tk * H; e += 256) {
        int r = e >> 9, c = e & (H - 1);
        ks[r * SP + c] = kvbuf[(long)(b * Tk + r) * kvstride + koff + c];
    }
    __syncthreads();

    // scores
    for (int idx = t; idx < NH * Tq * Tk; idx += 256) {
        int h = idx / (Tq * Tk);
        int rr = idx - h * Tq * Tk;
        int ti = rr / Tk, tj = rr - ti * Tk;
        int c0 = h * DH;
        float s = 0.f;
        #pragma unroll 16
        for (int d = 0; d < DH; d++) s += qs[ti * SP + c0 + d] * ks[tj * SP + c0 + d];
        sc[(h * MAXF + ti) * (TC + 1) + tj] = s * 0.125f;
    }
    __syncthreads();
    // softmax rows
    for (int idx = t; idx < NH * Tq; idx += 256) {
        int h = idx / Tq, ti = idx - h * Tq;
        float* row = &sc[(h * MAXF + ti) * (TC + 1)];
        float mx = -1e30f;
        for (int j = 0; j < Tk; j++) mx = fmaxf(mx, row[j]);
        float sum = 0.f;
        for (int j = 0; j < Tk; j++) { float e = expf(row[j] - mx); row[j] = e; sum += e; }
        float inv = 1.f / sum;
        for (int j = 0; j < Tk; j++) row[j] *= inv;
    }
    __syncthreads();
    // att = P @ V  (v read straight from gmem, L1-cached, reused Tq times)
    for (int e = t; e < Tq * H; e += 256) {
        int ti = e >> 9, c = e & (H - 1);
        int h = c >> 6;
        const float* p = &sc[(h * MAXF + ti) * (TC + 1)];
        float o = 0.f;
        for (int j = 0; j < Tk; j++)
            o += p[j] * kvbuf[(long)(b * Tk + j) * kvstride + voff + c];
        att[ti * SP + c] = o;
    }
    __syncthreads();

    // out-proj slice: 128 cols; 8 warps x 8n x 2 passes
    int w = t >> 5, lane = t & 31;
    for (int pass = 0; pass < 2; pass++) {
        int n0 = blockIdx.x * 128 + pass * 64 + w * 8;
        float acc[MAXF][8];
        #pragma unroll
        for (int i = 0; i < MAXF; i++)
            #pragma unroll
            for (int j = 0; j < 8; j++) acc[i][j] = 0.f;
        for (int kc = 0; kc < H; kc += 128) {
            float4 a[MAXF];
            for (int ti = 0; ti < Tq; ti++)
                a[ti] = *(const float4*)&att[ti * SP + kc + lane * 4];
            #pragma unroll
            for (int j = 0; j < 8; j++) {
                float4 bv = *(const float4*)(ow + (long)(n0 + j) * H + kc + lane * 4);
                for (int ti = 0; ti < Tq; ti++)
                    acc[ti][j] += a[ti].x * bv.x + a[ti].y * bv.y + a[ti].z * bv.z + a[ti].w * bv.w;
            }
        }
        for (int ti = 0; ti < Tq; ti++) {
            #pragma unroll
            for (int j = 0; j < 8; j++) {
                float v = acc[ti][j];
                v += __shfl_xor_sync(0xffffffffu, v, 16);
                v += __shfl_xor_sync(0xffffffffu, v, 8);
                v += __shfl_xor_sync(0xffffffffu, v, 4);
                v += __shfl_xor_sync(0xffffffffu, v, 2);
                v += __shfl_xor_sync(0xffffffffu, v, 1);
                if (lane == 0)
                    proj[(long)(b * Tq + ti) * H + n0 + j] = v + ob[n0 + j];
            }
        }
    }

    // atomic-tail residual + LN for this batch's rows
    __threadfence();
    __syncthreads();
    if (t == 0) s_last = (atomicAdd(&g_cnt[b], 1) == (int)gridDim.x - 1);
    __syncthreads();
    if (!s_last) return;
    __threadfence();

    for (int ti = 0; ti < Tq; ti++) {
        long row = b * Tq + ti;
        int c0 = t * 2;
        float2 pv = *(const float2*)&proj[row * H + c0];
        float2 rv;
        if (res_bcast) rv = *(const float2*)&res[(long)ti * H + c0];
        else           rv = *(const float2*)&res[row * H + c0];
        float v0 = pv.x + rv.x, v1 = pv.y + rv.y;
        float s1 = v0 + v1, s2 = v0 * v0 + v1 * v1;
        #pragma unroll
        for (int o = 16; o; o >>= 1) {
            s1 += __shfl_xor_sync(0xffffffffu, s1, o);
            s2 += __shfl_xor_sync(0xffffffffu, s2, o);
        }
        __syncthreads();
        if ((t & 31) == 0) { r1[t >> 5] = s1; r2[t >> 5] = s2; }
        __syncthreads();
        float S1 = 0.f, S2 = 0.f;
        #pragma unroll
        for (int i = 0; i < 8; i++) { S1 += r1[i]; S2 += r2[i]; }
        float mean = S1 * (1.f / H);
        float var = S2 * (1.f / H) - mean * mean;
        float inv = rsqrtf(var + 1e-5f);
        float2 lwv = *(const float2*)&lw[c0];
        float2 lbv = *(const float2*)&lb[c0];
        float2 y;
        y.x = (v0 - mean) * inv * lwv.x + lbv.x;
        y.y = (v1 - mean) * inv * lwv.y + lbv.y;
        *(float2*)&xout[row * H + c0] = y;
    }
    if (t == 0) g_cnt[b] = 0;
}

// ---------------- ff2 GEMM + residual + LN (+ optional final norm) ----------------
// grid (16, M/8); 128 threads. Last n-block per m-group does the LN tail.
__global__ void __launch_bounds__(128) k_gemm_ln(
    const float* __restrict__ A, const float* __restrict__ W,
    const float* __restrict__ bias, float* __restrict__ C,
    int K, int ldw,
    const float* __restrict__ res,
    const float* __restrict__ lw, const float* __restrict__ lb,
    float* __restrict__ xout,
    const float* __restrict__ fw, const float* __restrict__ fb,
    float* __restrict__ ctxout)
{
    int m0 = blockIdx.y * 8;
    gemm_body(A, W, bias, C, H, K, ldw, 0, m0, blockIdx.x * 32, 0);

    __shared__ int s_last;
    __shared__ float r1[4], r2[4];
    __threadfence();
    __syncthreads();
    if (threadIdx.x == 0)
        s_last = (atomicAdd(&g_cnt[blockIdx.y], 1) == (int)gridDim.x - 1);
    __syncthreads();
    if (!s_last) return;
    __threadfence();

    int t = threadIdx.x;
    int c0 = t * 4;
    float4 lwv = *(const float4*)&lw[c0];
    float4 lbv = *(const float4*)&lb[c0];
    for (int i = 0; i < 8; i++) {
        long row = m0 + i;
        float4 pv = *(const float4*)&C[row * H + c0];
        float4 rv = *(const float4*)&res[row * H + c0];
        float4 v = make_float4(pv.x + rv.x, pv.y + rv.y, pv.z + rv.z, pv.w + rv.w);
        float s1 = v.x + v.y + v.z + v.w;
        float s2 = v.x * v.x + v.y * v.y + v.z * v.z + v.w * v.w;
        #pragma unroll
        for (int o = 16; o; o >>= 1) {
            s1 += __shfl_xor_sync(0xffffffffu, s1, o);
            s2 += __shfl_xor_sync(0xffffffffu, s2, o);
        }
        __syncthreads();
        if ((t & 31) == 0) { r1[t >> 5] = s1; r2[t >> 5] = s2; }
        __syncthreads();
        float S1 = r1[0] + r1[1] + r1[2] + r1[3];
        float S2 = r2[0] + r2[1] + r2[2] + r2[3];
        float mean = S1 * (1.f / H);
        float var = S2 * (1.f / H) - mean * mean;
        float inv = rsqrtf(var + 1e-5f);
        float4 y;
        y.x = (v.x - mean) * inv * lwv.x + lbv.x;
        y.y = (v.y - mean) * inv * lwv.y + lbv.y;
        y.z = (v.z - mean) * inv * lwv.z + lbv.z;
        y.w = (v.w - mean) * inv * lwv.w + lbv.w;
        *(float4*)&xout[row * H + c0] = y;
        if (fw) {  // final norm on y -> ctxout
            float t1 = y.x + y.y + y.z + y.w;
            float t2 = y.x * y.x + y.y * y.y + y.z * y.z + y.w * y.w;
            #pragma unroll
            for (int o = 16; o; o >>= 1) {
                t1 += __shfl_xor_sync(0xffffffffu, t1, o);
                t2 += __shfl_xor_sync(0xffffffffu, t2, o);
            }
            __syncthreads();
            if ((t & 31) == 0) { r1[t >> 5] = t1; r2[t >> 5] = t2; }
            __syncthreads();
            float T1 = r1[0] + r1[1] + r1[2] + r1[3];
            float T2 = r2[0] + r2[1] + r2[2] + r2[3];
            float m2 = T1 * (1.f / H);
            float v2 = T2 * (1.f / H) - m2 * m2;
            float i2 = rsqrtf(v2 + 1e-5f);
            float4 fwv = *(const float4*)&fw[c0];
            float4 fbv = *(const float4*)&fb[c0];
            float4 z;
            z.x = (y.x - m2) * i2 * fwv.x + fbv.x;
            z.y = (y.y - m2) * i2 * fwv.y + fbv.y;
            z.z = (y.z - m2) * i2 * fwv.z + fbv.z;
            z.w = (y.w - m2) * i2 * fwv.w + fbv.w;
            *(float4*)&ctxout[row * H + c0] = z;
        }
    }
    if (t == 0) g_cnt[blockIdx.y] = 0;
}

// ---------------- head precompute: sW gemm + oW gemm + fused pe2 head weights ----------------
#define HP_G1 ((H/32) * (BSZ*NOBJ/8))   /* 640 blocks per gemm */
__global__ void __launch_bounds__(128) k_headpre(
    const float* __restrict__ objf, const float* __restrict__ pe1_w,
    const float* __restrict__ pred_w, const float* __restrict__ pred_b,
    const float* __restrict__ ex_w, const float* __restrict__ ex_b,
    const float* __restrict__ pe2_w, const float* __restrict__ pe2_b)
{
    int blk = blockIdx.x;
    if (blk < 2 * HP_G1) {
        int which = blk >= HP_G1;
        int idx = blk - which * HP_G1;
        int n0 = (idx & 15) * 32;
        int m0 = (idx >> 4) * 8;
        gemm_body(objf, pe1_w + which * H, nullptr, which ? g_ow : g_sw,
                  H, H, 3 * H, 0, m0, n0, 0);
        return;
    }
    int j = blk - 2 * HP_G1;  // 0..26
    const float* wc = (j < NPRED) ? (pred_w + j * H) : ex_w;
    int t = threadIdx.x;
    int c0 = t * 4;
    float4 s = make_float4(0.f, 0.f, 0.f, 0.f);
    for (int o = 0; o < H; o++) {
        float w = wc[o];
        float4 p = *(const float4*)&pe2_w[(long)o * H + c0];
        s.x += w * p.x; s.y += w * p.y; s.z += w * p.z; s.w += w * p.w;
    }
    *(float4*)&g_wf[j * H + c0] = s;
    // bias
    __shared__ float sm[4];
    float bsum = 0.f;
    for (int o = t; o < H; o += 128) bsum += wc[o] * pe2_b[o];
    #pragma unroll
    for (int o = 16; o; o >>= 1) bsum += __shfl_xor_sync(0xffffffffu, bsum, o);
    if ((t & 31) == 0) sm[t >> 5] = bsum;
    __syncthreads();
    if (t == 0) g_bf[j] = ((j < NPRED) ? pred_b[j] : ex_b[0]) + sm[0] + sm[1] + sm[2] + sm[3];
}

// ---------------- pair head: h = gelu(sW+oW+cW), out = h @ Wf^T + bf ----------------
// 256 threads = 8 warps; warp holds 8 rows in registers; 64 rows/block.
__global__ void __launch_bounds__(256) k_pair(
    const float* __restrict__ sW, const float* __restrict__ oW,
    const float* __restrict__ cW, float* __restrict__ out, int Fh, int Rtot)
{
    int w = threadIdx.x >> 5, lane = threadIdx.x & 31;
    int rbase = blockIdx.x * 64 + w * 8;
    float h[8][16];
    #pragma unroll
    for (int i = 0; i < 8; i++) {
        int row = rbase + i;
        if (row >= Rtot) {
            #pragma unroll
            for (int q = 0; q < 16; q++) h[i][q] = 0.f;
            continue;
        }
        int p = row % NP;
        int bfi = row / NP;
        int f = bfi % Fh;
        int b = bfi / Fh;
        int oi = p / (NOBJ - 1);
        int jr = p % (NOBJ - 1);
        int jo = jr + (jr >= oi ? 1 : 0);
        const float* sp = sW + (long)(b * NOBJ + oi) * H;
        const float* op = oW + (long)(b * NOBJ + jo) * H;
        const float* cp = cW + (long)(b * Fh + f) * H;
        #pragma unroll
        for (int q = 0; q < 4; q++) {
            int c = lane * 4 + q * 128;
            float4 sv = *(const float4*)(sp + c);
            float4 ov = *(const float4*)(op + c);
            float4 cv = *(const float4*)(cp + c);
            h[i][q * 4 + 0] = gelu_f(sv.x + ov.x + cv.x);
            h[i][q * 4 + 1] = gelu_f(sv.y + ov.y + cv.y);
            h[i][q * 4 + 2] = gelu_f(sv.z + ov.z + cv.z);
            h[i][q * 4 + 3] = gelu_f(sv.w + ov.w + cv.w);
        }
    }
    for (int j = 0; j < 27; j++) {
        float acc[8];
        #pragma unroll
        for (int i = 0; i < 8; i++) acc[i] = 0.f;
        #pragma unroll
        for (int q = 0; q < 4; q++) {
            float4 wv = *(const float4*)&g_wf[j * H + lane * 4 + q * 128];
            #pragma unroll
            for (int i = 0; i < 8; i++) {
                acc[i] += h[i][q * 4 + 0] * wv.x + h[i][q * 4 + 1] * wv.y
                        + h[i][q * 4 + 2] * wv.z + h[i][q * 4 + 3] * wv.w;
            }
        }
        float bfj = g_bf[j];
        #pragma unroll
        for (int i = 0; i < 8; i++) {
            float v = acc[i];
            v += __shfl_xor_sync(0xffffffffu, v, 16);
            v += __shfl_xor_sync(0xffffffffu, v, 8);
            v += __shfl_xor_sync(0xffffffffu, v, 4);
            v += __shfl_xor_sync(0xffffffffu, v, 2);
            v += __shfl_xor_sync(0xffffffffu, v, 1);
            if (lane == 0) {
                int row = rbase + i;
                if (row < Rtot) {
                    v += bfj;
                    if (j < NPRED) out[(long)row * NPRED + j] = v;
                    else           out[(long)Rtot * NPRED + row] = v;
                }
            }
        }
    }
}

// ---------------- host orchestration ----------------
extern "C" void kernel_launch(void* const* d_in, const int* in_sizes, int n_in,
                              void* d_out, int out_size)
{
    const float* tctx    = (const float*)d_in[0];
    const float* objf    = (const float*)d_in[1];
    const float* fq      = (const float*)d_in[2];
    const float* sa_in_w = (const float*)d_in[3];
    const float* sa_in_b = (const float*)d_in[4];
    const float* sa_out_w= (const float*)d_in[5];
    const float* sa_out_b= (const float*)d_in[6];
    const float* ca_in_w = (const float*)d_in[7];
    const float* ca_in_b = (const float*)d_in[8];
    const float* ca_out_w= (const float*)d_in[9];
    const float* ca_out_b= (const float*)d_in[10];
    const float* ff1_w   = (const float*)d_in[11];
    const float* ff1_b   = (const float*)d_in[12];
    const float* ff2_w   = (const float*)d_in[13];
    const float* ff2_b   = (const float*)d_in[14];
    const float* n1_w    = (const float*)d_in[15];
    const float* n1_b    = (const float*)d_in[16];
    const float* n2_w    = (const float*)d_in[17];
    const float* n2_b    = (const float*)d_in[18];
    const float* n3_w    = (const float*)d_in[19];
    const float* n3_b    = (const float*)d_in[20];
    const float* norm_w  = (const float*)d_in[21];
    const float* norm_b  = (const float*)d_in[22];
    const float* pe1_w   = (const float*)d_in[23];
    const float* pe1_b   = (const float*)d_in[24];
    const float* pe2_w   = (const float*)d_in[25];
    const float* pe2_b   = (const float*)d_in[26];
    const float* pred_w  = (const float*)d_in[27];
    const float* pred_b  = (const float*)d_in[28];
    const float* ex_w    = (const float*)d_in[29];
    const float* ex_b    = (const float*)d_in[30];
    (void)in_sizes; (void)n_in;

    int Fh = out_size / (BSZ * NP * (NPRED + 1));
    if (Fh < 1) Fh = 1;
    if (Fh > MAXF) Fh = MAXF;
    int Mq = BSZ * Fh;
    int MG = Mq / 8;

    float *px, *pqkv, *pkv, *patt, *pproj, *pffh, *pctx, *psw, *pow_, *pcw;
    cudaGetSymbolAddress((void**)&px,    g_px);
    cudaGetSymbolAddress((void**)&pqkv,  g_qkv);
    cudaGetSymbolAddress((void**)&pkv,   g_kv);
    cudaGetSymbolAddress((void**)&patt,  g_att);
    cudaGetSymbolAddress((void**)&pproj, g_proj);
    cudaGetSymbolAddress((void**)&pffh,  g_ffh);
    cudaGetSymbolAddress((void**)&pctx,  g_ctx);
    cudaGetSymbolAddress((void**)&psw,   g_sw);
    cudaGetSymbolAddress((void**)&pow_,  g_ow);
    cudaGetSymbolAddress((void**)&pcw,   g_cw);

    // 1) head precompute (independent of decoder)
    k_headpre<<<2 * HP_G1 + 27, 128>>>(objf, pe1_w, pred_w, pred_b, ex_w, ex_b, pe2_w, pe2_b);

    for (int l = 0; l < NLAY; l++) {
        const float* xin = px;
        int bc = 0;
        if (l == 0) { xin = fq; bc = Fh; }  // layer0 reads broadcast future_queries
        // 2) SA qkv
        k_gemm<<<dim3(48, MG), 128>>>(xin, sa_in_w + (long)l * 3 * H * H,
                                      sa_in_b + l * 3 * H, pqkv, 3 * H, H, H, 0, bc);
        // 3) SA attention + out-proj + residual + LN
        k_attn<<<dim3(4, BSZ), 256>>>(pqkv, 3 * H, pqkv, 3 * H, H, 2 * H,
                                      Fh, Fh,
                                      sa_out_w + (long)l * H * H, sa_out_b + l * H,
                                      (l == 0) ? fq : px, (l == 0) ? 1 : 0,
                                      n1_w + l * H, n1_b + l * H, patt, px);
        // 4) CA q + kv projections
        k_caqkv<<<dim3(32, 20, 2), 128>>>(px, tctx,
                                          ca_in_w + (long)l * 3 * H * H, ca_in_b + l * 3 * H,
                                          ca_in_w + (long)l * 3 * H * H + (long)H * H,
                                          ca_in_b + l * 3 * H + H,
                                          pqkv, pkv, Mq);
        // 5) CA attention + out-proj + residual + LN
        k_attn<<<dim3(4, BSZ), 256>>>(pqkv, H, pkv, 2 * H, 0, H,
                                      Fh, TC,
                                      ca_out_w + (long)l * H * H, ca_out_b + l * H,
                                      px, 0,
                                      n2_w + l * H, n2_b + l * H, patt, px);
        // 6) FF1 (gelu)
        k_gemm<<<dim3(64, MG), 128>>>(px, ff1_w + (long)l * FFD * H,
                                      ff1_b + l * FFD, pffh, FFD, H, H, 1, 0);
        // 7) FF2 + residual + LN (+ final norm on last layer)
        int last = (l == NLAY - 1);
        k_gemm_ln<<<dim3(16, MG), 128>>>(pffh, ff2_w + (long)l * H * FFD,
                                         ff2_b + l * H, pproj, FFD, FFD,
                                         px, n3_w + l * H, n3_b + l * H, px,
                                         last ? norm_w : nullptr,
                                         last ? norm_b : nullptr, pctx);
    }

    // 8) ctx projection through pe1 ctx slice
    k_gemm<<<dim3(16, MG), 128>>>(pctx, pe1_w + 2 * H, pe1_b, pcw, H, H, 3 * H, 0, 0);

    // 9) fused pair head
    int Rtot = BSZ * Fh * NP;
    k_pair<<<(Rtot + 63) / 64, 256>>>(psw, pow_, pcw, (float*)d_out, Fh, Rtot);
}

// round 10
// speedup vs baseline: 1.5609x; 1.5609x over previous
#include <cuda_runtime.h>
#include <math.h>

#define H    512
#define NH   8
#define DH   64
#define NLAY 2
#define NPRED 26
#define MAXF 5
#define FFD  2048
#define BSZ  16
#define TC   10
#define NOBJ 20
#define NP   380   /* NOBJ*(NOBJ-1) */

// ---------------- scratch (device globals; no allocation) ----------------
__device__ __align__(16) float g_px  [BSZ*MAXF*H];
__device__ __align__(16) float g_qkv [BSZ*MAXF*3*H];
__device__ __align__(16) float g_kv  [NLAY*BSZ*TC*2*H];
__device__ __align__(16) float g_att [BSZ*MAXF*H];
__device__ __align__(16) float g_proj[BSZ*MAXF*H];
__device__ __align__(16) float g_ffh [BSZ*MAXF*FFD];
__device__ __align__(16) float g_ctx [BSZ*MAXF*H];
__device__ __align__(16) float g_sw  [BSZ*NOBJ*H];
__device__ __align__(16) float g_ow  [BSZ*NOBJ*H];
__device__ __align__(16) float g_cw  [BSZ*MAXF*H];
__device__ __align__(16) float g_wf  [27*H];
__device__ float g_bf [32];

__device__ __forceinline__ float gelu_f(float x) {
    return 0.5f * x * (1.0f + erff(x * 0.70710678118654752440f));
}

// packed f32x2 FMA: d(lo,hi) += a(lo,hi) * b(lo,hi)   (sm_103a FFMA2, PTX-only)
__device__ __forceinline__ void ffma2(unsigned long long& d, unsigned long long a,
                                      unsigned long long b) {
    asm("fma.rn.f32x2 %0, %1, %2, %0;" : "+l"(d) : "l"(a), "l"(b));
}
__device__ __forceinline__ float unpack_sum(unsigned long long v) {
    return __uint_as_float((unsigned)(v & 0xffffffffull)) +
           __uint_as_float((unsigned)(v >> 32));
}

// ---------------- f32x2 warp-dot GEMM body (128 threads): 4m x 32n per block ----
// C[M,N] = act(A[M,K] @ W[N,ldw]^T + bias). K % 128 == 0, rows 16B-aligned.
// Each warp: 4m x 8n; lane l owns the float4 k-slice at k + 4*l per 128-chunk.
// bcmod>0: A row m reads A + (m % bcmod)*K (broadcast rows).
__device__ __forceinline__ void gemm2_body(
    const float* __restrict__ A, const float* __restrict__ W,
    const float* __restrict__ bias, float* __restrict__ C,
    int N, int K, int ldw, int act, int m0, int n0, int bcmod)
{
    int warp = threadIdx.x >> 5, lane = threadIdx.x & 31;
    n0 += warp * 8;
    const float* Ar[4];
    #pragma unroll
    for (int i = 0; i < 4; i++) {
        int m = m0 + i;
        int mm = bcmod ? (m % bcmod) : m;
        Ar[i] = A + (long)mm * K + lane * 4;
    }
    const float* Wb = W + (long)n0 * ldw + lane * 4;

    unsigned long long acc[4][8];
    #pragma unroll
    for (int i = 0; i < 4; i++)
        #pragma unroll
        for (int j = 0; j < 8; j++) acc[i][j] = 0ull;

    for (int k = 0; k < K; k += 128) {
        ulonglong2 av[4];
        #pragma unroll
        for (int i = 0; i < 4; i++)
            av[i] = *(const ulonglong2*)(Ar[i] + k);
        #pragma unroll
        for (int j = 0; j < 8; j++) {
            ulonglong2 bv = *(const ulonglong2*)(Wb + (long)j * ldw + k);
            #pragma unroll
            for (int i = 0; i < 4; i++) {
                ffma2(acc[i][j], av[i].x, bv.x);
                ffma2(acc[i][j], av[i].y, bv.y);
            }
        }
    }

    #pragma unroll
    for (int i = 0; i < 4; i++)
        #pragma unroll
        for (int j = 0; j < 8; j++) {
            float v = unpack_sum(acc[i][j]);
            v += __shfl_xor_sync(0xffffffffu, v, 16);
            v += __shfl_xor_sync(0xffffffffu, v, 8);
            v += __shfl_xor_sync(0xffffffffu, v, 4);
            v += __shfl_xor_sync(0xffffffffu, v, 2);
            v += __shfl_xor_sync(0xffffffffu, v, 1);
            if (lane == 0) {
                int n = n0 + j;
                float r = v + (bias ? bias[n] : 0.f);
                if (act) r = gelu_f(r);
                C[(long)(m0 + i) * N + n] = r;
            }
        }
}

__global__ void __launch_bounds__(128) k_gemm(
    const float* __restrict__ A, const float* __restrict__ W,
    const float* __restrict__ bias, float* __restrict__ C,
    int N, int K, int ldw, int act, int bcmod)
{
    gemm2_body(A, W, bias, C, N, K, ldw, act, blockIdx.y * 4, blockIdx.x * 32, bcmod);
}

// ---------------- head precompute mega-kernel (all decoder-independent work) ----
// [0,1280)        sW  = objf @ pe1_w[0:H]^T          (320 x H)
// [1280,2560)     oW  = objf @ pe1_w[H:2H]^T         (320 x H)
// [2560,3840)     kv layer0 = tctx @ ca_in_w0[H:3H]^T (160 x 2H)
// [3840,5120)     kv layer1 = tctx @ ca_in_w1[H:3H]^T (160 x 2H)
// [5120,5147)     fused head weights g_wf/g_bf (27 rows)
#define G_OBJ ((H/32) * (BSZ*NOBJ/4))     /* 16*80 = 1280 */
#define G_KV  ((2*H/32) * (BSZ*TC/4))     /* 32*40 = 1280 */
__global__ void __launch_bounds__(128) k_headpre(
    const float* __restrict__ objf, const float* __restrict__ tctx,
    const float* __restrict__ pe1_w,
    const float* __restrict__ ca_in_w, const float* __restrict__ ca_in_b,
    const float* __restrict__ pred_w, const float* __restrict__ pred_b,
    const float* __restrict__ ex_w, const float* __restrict__ ex_b,
    const float* __restrict__ pe2_w, const float* __restrict__ pe2_b)
{
    int blk = blockIdx.x;
    if (blk < 2 * G_OBJ) {
        int which = blk >= G_OBJ;
        int idx = blk - which * G_OBJ;
        int n0 = (idx & 15) * 32;
        int m0 = (idx >> 4) * 4;
        gemm2_body(objf, pe1_w + which * H, nullptr, which ? g_ow : g_sw,
                   H, H, 3 * H, 0, m0, n0, 0);
        return;
    }
    blk -= 2 * G_OBJ;
    if (blk < 2 * G_KV) {
        int l = blk >= G_KV;
        int idx = blk - l * G_KV;
        int n0 = (idx & 31) * 32;
        int m0 = (idx >> 5) * 4;
        gemm2_body(tctx, ca_in_w + (long)l * 3 * H * H + (long)H * H,
                   ca_in_b + l * 3 * H + H,
                   g_kv + (long)l * BSZ * TC * 2 * H,
                   2 * H, H, H, 0, m0, n0, 0);
        return;
    }
    int j = blk - 2 * G_KV;  // 0..26
    const float* wc = (j < NPRED) ? (pred_w + j * H) : ex_w;
    int t = threadIdx.x;
    int c0 = t * 4;
    float4 s = make_float4(0.f, 0.f, 0.f, 0.f);
    for (int o = 0; o < H; o++) {
        float w = wc[o];
        float4 p = *(const float4*)&pe2_w[(long)o * H + c0];
        s.x += w * p.x; s.y += w * p.y; s.z += w * p.z; s.w += w * p.w;
    }
    *(float4*)&g_wf[j * H + c0] = s;
    __shared__ float sm[4];
    float bsum = 0.f;
    for (int o = t; o < H; o += 128) bsum += wc[o] * pe2_b[o];
    #pragma unroll
    for (int o = 16; o; o >>= 1) bsum += __shfl_xor_sync(0xffffffffu, bsum, o);
    if ((t & 31) == 0) sm[t >> 5] = bsum;
    __syncthreads();
    if (t == 0) g_bf[j] = ((j < NPRED) ? pred_b[j] : ex_b[0]) + sm[0] + sm[1] + sm[2] + sm[3];
}

// ---------------- tiny multi-head attention: one block per (head, batch) --------
__global__ void attn_kernel(const float* __restrict__ q, int qstride,
                            const float* __restrict__ k, const float* __restrict__ v, int kvstride,
                            float* __restrict__ out,
                            int Tq, int Tk, float scale)
{
    int h = blockIdx.x, b = blockIdx.y;
    __shared__ float qs[MAXF][DH], ks[TC][DH], vs[TC][DH], sc[MAXF][TC];
    int t = threadIdx.x;  // 64
    for (int i = 0; i < Tq; i++) qs[i][t] = q[(long)(b * Tq + i) * qstride + h * DH + t];
    for (int j = 0; j < Tk; j++) {
        ks[j][t] = k[(long)(b * Tk + j) * kvstride + h * DH + t];
        vs[j][t] = v[(long)(b * Tk + j) * kvstride + h * DH + t];
    }
    __syncthreads();
    if (t < Tq * Tk) {
        int ti = t / Tk, tj = t % Tk;
        float s = 0.f;
        #pragma unroll
        for (int d = 0; d < DH; d++) s += qs[ti][d] * ks[tj][d];
        sc[ti][tj] = s * scale;
    }
    __syncthreads();
    if (t < Tq) {
        float mx = -1e30f;
        for (int j = 0; j < Tk; j++) mx = fmaxf(mx, sc[t][j]);
        float sum = 0.f;
        for (int j = 0; j < Tk; j++) { float e = expf(sc[t][j] - mx); sc[t][j] = e; sum += e; }
        float inv = 1.f / sum;
        for (int j = 0; j < Tk; j++) sc[t][j] *= inv;
    }
    __syncthreads();
    for (int ti = 0; ti < Tq; ti++) {
        float o = 0.f;
        for (int j = 0; j < Tk; j++) o += sc[ti][j] * vs[j][t];
        out[(long)(b * Tq + ti) * H + h * DH + t] = o;
    }
}

// ---------------- layernorm: out = LN(x + res)(w,b); optional 2nd LN -> ctx -----
// one block per row, 128 threads. resmod>0: res row index = row % resmod.
__global__ void ln_kernel(const float* __restrict__ x, const float* __restrict__ res,
                          int resmod,
                          const float* __restrict__ w, const float* __restrict__ b,
                          float* __restrict__ out,
                          const float* __restrict__ fw, const float* __restrict__ fb,
                          float* __restrict__ ctxout)
{
    int row = blockIdx.x;
    int t = threadIdx.x;
    __shared__ float sm1[4], sm2[4];
    float v[4];
    long rrow = resmod ? (row % resmod) : row;
    float s1 = 0.f, s2 = 0.f;
    #pragma unroll
    for (int i = 0; i < 4; i++) {
        int c = t + i * 128;
        float val = x[(long)row * H + c] + res[rrow * H + c];
        v[i] = val; s1 += val; s2 += val * val;
    }
    #pragma unroll
    for (int o = 16; o; o >>= 1) {
        s1 += __shfl_xor_sync(0xffffffffu, s1, o);
        s2 += __shfl_xor_sync(0xffffffffu, s2, o);
    }
    if ((t & 31) == 0) { sm1[t >> 5] = s1; sm2[t >> 5] = s2; }
    __syncthreads();
    float S1 = sm1[0] + sm1[1] + sm1[2] + sm1[3];
    float S2 = sm2[0] + sm2[1] + sm2[2] + sm2[3];
    float mean = S1 * (1.f / H);
    float var = S2 * (1.f / H) - mean * mean;
    float inv = rsqrtf(var + 1e-5f);
    float y[4];
    #pragma unroll
    for (int i = 0; i < 4; i++) {
        int c = t + i * 128;
        y[i] = (v[i] - mean) * inv * w[c] + b[c];
        out[(long)row * H + c] = y[i];
    }
    if (fw) {
        float t1 = 0.f, t2 = 0.f;
        #pragma unroll
        for (int i = 0; i < 4; i++) { t1 += y[i]; t2 += y[i] * y[i]; }
        #pragma unroll
        for (int o = 16; o; o >>= 1) {
            t1 += __shfl_xor_sync(0xffffffffu, t1, o);
            t2 += __shfl_xor_sync(0xffffffffu, t2, o);
        }
        __syncthreads();
        if ((t & 31) == 0) { sm1[t >> 5] = t1; sm2[t >> 5] = t2; }
        __syncthreads();
        float T1 = sm1[0] + sm1[1] + sm1[2] + sm1[3];
        float T2 = sm2[0] + sm2[1] + sm2[2] + sm2[3];
        float m2 = T1 * (1.f / H);
        float v2 = T2 * (1.f / H) - m2 * m2;
        float i2 = rsqrtf(v2 + 1e-5f);
        #pragma unroll
        for (int i = 0; i < 4; i++) {
            int c = t + i * 128;
            ctxout[(long)row * H + c] = (y[i] - m2) * i2 * fw[c] + fb[c];
        }
    }
}

// ---------------- fused pair head: h = gelu(sW+oW+cW), out = h @ Wf^T + bf ------
__global__ void __launch_bounds__(256) pair_kernel(
    const float* __restrict__ sW, const float* __restrict__ oW,
    const float* __restrict__ cW,
    const float* __restrict__ wf, const float* __restrict__ bf,
    float* __restrict__ out, int Fh, int Rtot)
{
    __shared__ float hs[16][H];
    int t = threadIdx.x;  // 256
    int row0 = blockIdx.x * 16;

    for (int e = t; e < 16 * H; e += 256) {
        int r = e >> 9, c = e & (H - 1);
        int row = row0 + r;
        float hv = 0.f;
        if (row < Rtot) {
            int p = row % NP;
            int bfi = row / NP;
            int f = bfi % Fh;
            int b = bfi / Fh;
            int i = p / (NOBJ - 1);
            int jr = p % (NOBJ - 1);
            int jo = jr + (jr >= i ? 1 : 0);
            hv = sW[(long)(b * NOBJ + i) * H + c] + oW[(long)(b * NOBJ + jo) * H + c]
               + cW[(long)(b * Fh + f) * H + c];
            hv = gelu_f(hv);
        }
        hs[r][c] = hv;
    }
    __syncthreads();

    int w = t >> 5, lane = t & 31;
    for (int o = w; o < 16 * 27; o += 8) {
        int r = o & 15, j = o >> 4;
        float acc = 0.f;
        #pragma unroll
        for (int qq = 0; qq < 4; qq++) {
            int c = lane * 4 + qq * 128;
            float4 hv = *(const float4*)&hs[r][c];
            float4 wv = *(const float4*)&wf[j * H + c];
            acc += hv.x * wv.x + hv.y * wv.y + hv.z * wv.z + hv.w * wv.w;
        }
        #pragma unroll
        for (int off = 16; off; off >>= 1) acc += __shfl_xor_sync(0xffffffffu, acc, off);
        if (lane == 0) {
            int row = row0 + r;
            if (row < Rtot) {
                acc += bf[j];
                if (j < NPRED) out[(long)row * NPRED + j] = acc;
                else           out[(long)Rtot * NPRED + row] = acc;
            }
        }
    }
}

// ---------------- host orchestration ----------------
static inline void launch_gemm(const float* A, const float* W, const float* bias, float* C,
                               int M, int N, int K, int ldw, int act, int bcmod)
{
    dim3 grid(N / 32, M / 4);
    k_gemm<<<grid, 128>>>(A, W, bias, C, N, K, ldw, act, bcmod);
}

extern "C" void kernel_launch(void* const* d_in, const int* in_sizes, int n_in,
                              void* d_out, int out_size)
{
    const float* tctx    = (const float*)d_in[0];
    const float* objf    = (const float*)d_in[1];
    const float* fq      = (const float*)d_in[2];
    const float* sa_in_w = (const float*)d_in[3];
    const float* sa_in_b = (const float*)d_in[4];
    const float* sa_out_w= (const float*)d_in[5];
    const float* sa_out_b= (const float*)d_in[6];
    const float* ca_in_w = (const float*)d_in[7];
    const float* ca_in_b = (const float*)d_in[8];
    const float* ca_out_w= (const float*)d_in[9];
    const float* ca_out_b= (const float*)d_in[10];
    const float* ff1_w   = (const float*)d_in[11];
    const float* ff1_b   = (const float*)d_in[12];
    const float* ff2_w   = (const float*)d_in[13];
    const float* ff2_b   = (const float*)d_in[14];
    const float* n1_w    = (const float*)d_in[15];
    const float* n1_b    = (const float*)d_in[16];
    const float* n2_w    = (const float*)d_in[17];
    const float* n2_b    = (const float*)d_in[18];
    const float* n3_w    = (const float*)d_in[19];
    const float* n3_b    = (const float*)d_in[20];
    const float* norm_w  = (const float*)d_in[21];
    const float* norm_b  = (const float*)d_in[22];
    const float* pe1_w   = (const float*)d_in[23];
    const float* pe1_b   = (const float*)d_in[24];
    const float* pe2_w   = (const float*)d_in[25];
    const float* pe2_b   = (const float*)d_in[26];
    const float* pred_w  = (const float*)d_in[27];
    const float* pred_b  = (const float*)d_in[28];
    const float* ex_w    = (const float*)d_in[29];
    const float* ex_b    = (const float*)d_in[30];
    (void)in_sizes; (void)n_in;

    int Fh = out_size / (BSZ * NP * (NPRED + 1));
    if (Fh < 1) Fh = 1;
    if (Fh > MAXF) Fh = MAXF;
    int Mq = BSZ * Fh;

    float *px, *pqkv, *pkv, *patt, *pproj, *pffh, *pctx, *psw, *pow_, *pcw, *pwf, *pbf;
    cudaGetSymbolAddress((void**)&px,    g_px);
    cudaGetSymbolAddress((void**)&pqkv,  g_qkv);
    cudaGetSymbolAddress((void**)&pkv,   g_kv);
    cudaGetSymbolAddress((void**)&patt,  g_att);
    cudaGetSymbolAddress((void**)&pproj, g_proj);
    cudaGetSymbolAddress((void**)&pffh,  g_ffh);
    cudaGetSymbolAddress((void**)&pctx,  g_ctx);
    cudaGetSymbolAddress((void**)&psw,   g_sw);
    cudaGetSymbolAddress((void**)&pow_,  g_ow);
    cudaGetSymbolAddress((void**)&pcw,   g_cw);
    cudaGetSymbolAddress((void**)&pwf,   g_wf);
    cudaGetSymbolAddress((void**)&pbf,   g_bf);

    // 1) all decoder-independent precompute in one launch
    k_headpre<<<2 * G_OBJ + 2 * G_KV + 27, 128>>>(objf, tctx, pe1_w,
                                                  ca_in_w, ca_in_b,
                                                  pred_w, pred_b, ex_w, ex_b,
                                                  pe2_w, pe2_b);

    const float scale = 0.125f;  // 1/sqrt(64)
    for (int l = 0; l < NLAY; l++) {
        // SA qkv (layer0 reads broadcast future_queries directly)
        launch_gemm((l == 0) ? fq : px, sa_in_w + (long)l * 3 * H * H,
                    sa_in_b + l * 3 * H, pqkv, Mq, 3 * H, H, H, 0,
                    (l == 0) ? Fh : 0);
        attn_kernel<<<dim3(NH, BSZ), 64>>>(pqkv, 3 * H, pqkv + H, pqkv + 2 * H, 3 * H,
                                           patt, Fh, Fh, scale);
        launch_gemm(patt, sa_out_w + (long)l * H * H, sa_out_b + l * H, pproj,
                    Mq, H, H, H, 0, 0);
        ln_kernel<<<Mq, 128>>>(pproj, (l == 0) ? fq : px, (l == 0) ? Fh : 0,
                               n1_w + l * H, n1_b + l * H, px, nullptr, nullptr, nullptr);
        // CA (kv precomputed in headpre)
        launch_gemm(px, ca_in_w + (long)l * 3 * H * H, ca_in_b + l * 3 * H,
                    pqkv, Mq, H, H, H, 0, 0);
        const float* kvl = pkv + (long)l * BSZ * TC * 2 * H;
        attn_kernel<<<dim3(NH, BSZ), 64>>>(pqkv, H, kvl, kvl + H, 2 * H,
                                           patt, Fh, TC, scale);
        launch_gemm(patt, ca_out_w + (long)l * H * H, ca_out_b + l * H, pproj,
                    Mq, H, H, H, 0, 0);
        ln_kernel<<<Mq, 128>>>(pproj, px, 0, n2_w + l * H, n2_b + l * H, px,
                               nullptr, nullptr, nullptr);
        // FFN
        launch_gemm(px, ff1_w + (long)l * FFD * H, ff1_b + l * FFD, pffh,
                    Mq, FFD, H, H, 1, 0);
        launch_gemm(pffh, ff2_w + (long)l * H * FFD, ff2_b + l * H, pproj,
                    Mq, H, FFD, FFD, 0, 0);
        int last = (l == NLAY - 1);
        ln_kernel<<<Mq, 128>>>(pproj, px, 0, n3_w + l * H, n3_b + l * H, px,
                               last ? norm_w : nullptr, last ? norm_b : nullptr, pctx);
    }

    // ctx projection through pe1 ctx slice
    launch_gemm(pctx, pe1_w + 2 * H, pe1_b, pcw, Mq, H, H, 3 * H, 0, 0);

    // fused pair head
    int Rtot = BSZ * Fh * NP;
    pair_kernel<<<(Rtot + 15) / 16, 256>>>(psw, pow_, pcw, pwf, pbf, (float*)d_out, Fh, Rtot);
}